// round 14
// baseline (speedup 1.0000x reference)
#include <cuda_runtime.h>
#include <cuda_fp16.h>
#include <cstdint>
#include <math.h>

// Problem constants
#define N_TOK   8192
#define DDIM    1024
#define FDIM    4096
#define NEXP    8
#define CAP     1280          // int(8192/8 * 1.25)
#define SLOTS_PER_E (2*CAP)   // 2560
#define TOT_SLOTS (NEXP*SLOTS_PER_E)

// fp16 GEMM tiling: R7 config (best mainloop)
#define STAGES  4
#define BKH     32                  // halves per K-chunk
#define HSTRIDE 40                  // halves per smem row (32 + 8 pad -> 80B)
#define A_ROWS  256
#define B_ROWS  128
#define ASTG    (A_ROWS*HSTRIDE)
#define BSTG    (B_ROWS*HSTRIDE)
#define STG_H   (ASTG+BSTG)
#define SMEM_BYTES (STAGES*STG_H*2) // 122880

// ---------------- scratch (static __device__, no runtime allocs) ----------------
__device__ __half g_xh[(size_t)N_TOK*DDIM];             // fp16 x
__device__ __half g_wgh[(size_t)NEXP*FDIM*DDIM];        // fp16 wi_gate
__device__ __half g_wuh[(size_t)NEXP*FDIM*DDIM];        // fp16 wi_up
__device__ __half g_woh[(size_t)NEXP*DDIM*FDIM];        // fp16 wo
__device__ __half g_hh[(size_t)NEXP*SLOTS_PER_E*FDIM];  // fp16 fused activation
__device__ int   g_tok[TOT_SLOTS];
__device__ float g_wgt[TOT_SLOTS];
__device__ int   g_eids[N_TOK*2];
__device__ float g_ew[N_TOK*2];
__device__ float g_probs[N_TOK*NEXP];
__device__ float g_lse[N_TOK];
__device__ int   g_cnt[2*NEXP];

// ---------------- helpers ----------------
__device__ __forceinline__ void cp_async16(void* dst, const void* src, int bytes)
{
    unsigned s = (unsigned)__cvta_generic_to_shared(dst);
    asm volatile("cp.async.ca.shared.global [%0], [%1], 16, %2;\n"
                 :: "r"(s), "l"(src), "r"(bytes));
}
__device__ __forceinline__ void cp_commit() { asm volatile("cp.async.commit_group;\n"); }
__device__ __forceinline__ void cp_wait()   { asm volatile("cp.async.wait_group %0;\n" :: "n"(STAGES-2)); }

__device__ __forceinline__ void mma_f16(float* c, const unsigned* a, const unsigned* b)
{
    asm volatile(
        "mma.sync.aligned.m16n8k16.row.col.f32.f16.f16.f32 "
        "{%0,%1,%2,%3}, {%4,%5,%6,%7}, {%8,%9}, {%0,%1,%2,%3};\n"
        : "+f"(c[0]), "+f"(c[1]), "+f"(c[2]), "+f"(c[3])
        : "r"(a[0]), "r"(a[1]), "r"(a[2]), "r"(a[3]), "r"(b[0]), "r"(b[1]));
}

__device__ __forceinline__ void ldsm_x4(unsigned* r, unsigned addr)
{
    asm volatile("ldmatrix.sync.aligned.m8n8.x4.shared.b16 {%0,%1,%2,%3}, [%4];"
                 : "=r"(r[0]), "=r"(r[1]), "=r"(r[2]), "=r"(r[3]) : "r"(addr));
}

__device__ __forceinline__ float silu_mul(float g, float u)
{
    return g / (1.f + expf(-g)) * u;
}

// ---------------- fp32 -> fp16 converts (pipelined per expert) ----------------
#define NX2 (N_TOK*DDIM/2)
#define NW2 (NEXP*FDIM*DDIM/2)
#define NWE2 (FDIM*DDIM/2)        // one expert's wg (or wu) slice in half2 units

__global__ void __launch_bounds__(256) conv_x(const float2* __restrict__ x)
{
    int stride = gridDim.x * blockDim.x;
    for (int i = blockIdx.x*blockDim.x + threadIdx.x; i < NX2; i += stride)
        ((__half2*)g_xh)[i] = __float22half2_rn(x[i]);
}

__global__ void __launch_bounds__(256) conv_wgu_e(const float2* __restrict__ wg,
                                                  const float2* __restrict__ wu,
                                                  int e)
{
    size_t base = (size_t)e * NWE2;
    int stride = gridDim.x * blockDim.x;
    for (int i = blockIdx.x*blockDim.x + threadIdx.x; i < NWE2; i += stride) {
        ((__half2*)g_wgh)[base + i] = __float22half2_rn(wg[base + i]);
        ((__half2*)g_wuh)[base + i] = __float22half2_rn(wu[base + i]);
    }
}

__global__ void __launch_bounds__(256) conv_wo(const float2* __restrict__ wo)
{
    long long stride = (long long)gridDim.x * blockDim.x;
    for (long long i = (long long)blockIdx.x*blockDim.x + threadIdx.x; i < NW2; i += stride)
        ((__half2*)g_woh)[i] = __float22half2_rn(wo[i]);
}

// ---------------- zero output (atomic accumulate base) ----------------
__global__ void __launch_bounds__(256) zero_out_kernel(float4* __restrict__ out4)
{
    int i = blockIdx.x * 256 + threadIdx.x;
    out4[i] = make_float4(0.f, 0.f, 0.f, 0.f);
}

// ---------------- router: logits, softmax, top-2, weights ----------------
__global__ void __launch_bounds__(256) router_kernel(const float* __restrict__ x,
                                                     const float* __restrict__ gw)
{
    int t = blockIdx.x;
    const float* xr = x + (size_t)t * DDIM;
    __shared__ float sred[NEXP][256];
    float acc[NEXP];
#pragma unroll
    for (int e = 0; e < NEXP; e++) acc[e] = 0.f;
    for (int d = threadIdx.x; d < DDIM; d += 256) {
        float xv = xr[d];
#pragma unroll
        for (int e = 0; e < NEXP; e++) acc[e] += xv * gw[e*DDIM + d];
    }
#pragma unroll
    for (int e = 0; e < NEXP; e++) sred[e][threadIdx.x] = acc[e];
    __syncthreads();
    for (int s = 128; s > 0; s >>= 1) {
        if (threadIdx.x < s) {
#pragma unroll
            for (int e = 0; e < NEXP; e++) sred[e][threadIdx.x] += sred[e][threadIdx.x + s];
        }
        __syncthreads();
    }
    if (threadIdx.x == 0) {
        float lg[NEXP];
#pragma unroll
        for (int e = 0; e < NEXP; e++) lg[e] = sred[e][0];
        float mx = lg[0];
#pragma unroll
        for (int e = 1; e < NEXP; e++) mx = fmaxf(mx, lg[e]);
        float se = 0.f, p[NEXP];
#pragma unroll
        for (int e = 0; e < NEXP; e++) { p[e] = expf(lg[e] - mx); se += p[e]; }
        float inv = 1.f / se;
#pragma unroll
        for (int e = 0; e < NEXP; e++) { p[e] *= inv; g_probs[t*NEXP + e] = p[e]; }
        g_lse[t] = mx + logf(se);
        int i0 = 0;
#pragma unroll
        for (int e = 1; e < NEXP; e++) if (p[e] > p[i0]) i0 = e;
        int i1 = -1;
#pragma unroll
        for (int e = 0; e < NEXP; e++) {
            if (e == i0) continue;
            if (i1 < 0 || p[e] > p[i1]) i1 = e;
        }
        float s2 = p[i0] + p[i1];
        g_eids[t*2 + 0] = i0; g_eids[t*2 + 1] = i1;
        g_ew[t*2 + 0] = p[i0] / s2; g_ew[t*2 + 1] = p[i1] / s2;
    }
}

// ---------------- rank + clear + build fused (1024 threads, shfl-scan) ----------------
__global__ void __launch_bounds__(1024) rank_build_kernel()
{
    int k = blockIdx.x >> 3;
    int e = blockIdx.x & 7;
    int segbase = e*SLOTS_PER_E + k*CAP;
    int tid = threadIdx.x;
    for (int i = tid; i < CAP; i += 1024) {
        g_tok[segbase + i] = -1;
        g_wgt[segbase + i] = 0.f;
    }

    __shared__ int warp_sums[32];
    __shared__ int s_base;
    if (tid == 0) s_base = 0;
    __syncthreads();
    int lane = tid & 31, wid = tid >> 5;
    for (int c = 0; c < N_TOK; c += 1024) {
        int t = c + tid;
        int flag = (g_eids[t*2 + k] == e) ? 1 : 0;
        unsigned m = __ballot_sync(0xffffffffu, flag);
        int pre = __popc(m & ((1u << lane) - 1u));
        if (lane == 31) warp_sums[wid] = pre + flag;
        __syncthreads();
        if (wid == 0) {
            int v = warp_sums[lane];
#pragma unroll
            for (int o = 1; o < 32; o <<= 1) {
                int n = __shfl_up_sync(0xffffffffu, v, o);
                if (lane >= o) v += n;
            }
            warp_sums[lane] = v;   // inclusive scan
        }
        __syncthreads();
        int wbase = s_base + (wid ? warp_sums[wid-1] : 0);
        if (flag) {
            int r = wbase + pre;
            if (r < CAP) {
                g_tok[segbase + r] = t;
                g_wgt[segbase + r] = g_ew[t*2 + k];
            }
        }
        __syncthreads();
        if (tid == 0) s_base += warp_sums[31];
        __syncthreads();
    }
    if (tid == 0) g_cnt[k*NEXP + e] = s_base;
}

// ---------------- fused GEMM1 (fp16 mma + ldmatrix), per-expert, 256x(64+64) tile ----------------
// grid: (FDIM/64, SLOTS_PER_E/256), block 512, dyn smem
__global__ void __launch_bounds__(512, 1) gemm1_h(int e)
{
    int m0 = blockIdx.y * 256;
    int seg = (m0 >= CAP) ? 1 : 0;
    int lim = min(g_cnt[seg*NEXP + e], CAP);
    if ((m0 - seg*CAP) >= lim) return;

    int n0 = blockIdx.x * 64;

    extern __shared__ __half smh[];
    unsigned smu = (unsigned)__cvta_generic_to_shared(smh);

    int tid = threadIdx.x;
    int ar = tid >> 1;
    int hc = (tid & 1) * 16;
    int tok = g_tok[e*SLOTS_PER_E + m0 + ar];
    const __half* ap = g_xh + (size_t)max(tok, 0) * DDIM + hc;
    int abytes = (tok >= 0) ? 16 : 0;
    int br = tid >> 2;
    int bo = (tid & 3) * 8;
    const __half* bp = (br < 64)
        ? (g_wgh + ((size_t)e*FDIM + n0 + br) * DDIM + bo)
        : (g_wuh + ((size_t)e*FDIM + n0 + (br - 64)) * DDIM + bo);

    const int KT = DDIM / BKH;           // 32

#pragma unroll
    for (int s = 0; s < STAGES-1; s++) {
        __half* sA = smh + s*STG_H + ar*HSTRIDE + hc;
        __half* sB = smh + s*STG_H + ASTG + br*HSTRIDE + bo;
        int k0 = s * BKH;
        cp_async16(sA,      ap + k0,      abytes);
        cp_async16(sA + 8,  ap + k0 + 8,  abytes);
        cp_async16(sB,      bp + k0,      16);
        cp_commit();
    }

    float accg[4][2][4], accu[4][2][4];
#pragma unroll
    for (int a = 0; a < 4; a++)
#pragma unroll
        for (int b = 0; b < 2; b++)
#pragma unroll
            for (int c = 0; c < 4; c++) { accg[a][b][c] = 0.f; accu[a][b][c] = 0.f; }

    int wid = tid >> 5, lane = tid & 31;
    int wm = wid & 3, wn = wid >> 2;      // 4 m-warps(64 rows) x 4 n-warps(16 cols)
    int g = lane >> 2, tg = lane & 3;
    int l8 = lane & 7, g1 = lane >> 3;

    unsigned aoff[4];
#pragma unroll
    for (int mt = 0; mt < 4; mt++)
        aoff[mt] = ((wm*64 + mt*16 + (g1 & 1)*8 + l8) * HSTRIDE + (g1 >> 1)*8) * 2;
    unsigned bgoff = ((wn*16 + (g1 >> 1)*8 + l8) * HSTRIDE + (g1 & 1)*8) * 2 + ASTG*2;
    unsigned buoff = ((64 + wn*16 + (g1 >> 1)*8 + l8) * HSTRIDE + (g1 & 1)*8) * 2 + ASTG*2;

    for (int kt = 0; kt < KT; kt++) {
        cp_wait();
        __syncthreads();
        int pf = kt + STAGES - 1;
        if (pf < KT) {
            int st = pf % STAGES;
            __half* sA = smh + st*STG_H + ar*HSTRIDE + hc;
            __half* sB = smh + st*STG_H + ASTG + br*HSTRIDE + bo;
            int k0 = pf * BKH;
            cp_async16(sA,      ap + k0,      abytes);
            cp_async16(sA + 8,  ap + k0 + 8,  abytes);
            cp_async16(sB,      bp + k0,      16);
        }
        cp_commit();
        unsigned stOff = smu + (kt % STAGES)*(STG_H*2);
#pragma unroll
        for (int kk = 0; kk < 2; kk++) {
            unsigned kb = kk * 32;
            unsigned af[4][4], bg[4], bu[4];
#pragma unroll
            for (int mt = 0; mt < 4; mt++) ldsm_x4(af[mt], stOff + aoff[mt] + kb);
            ldsm_x4(bg, stOff + bgoff + kb);
            ldsm_x4(bu, stOff + buoff + kb);
#pragma unroll
            for (int mt = 0; mt < 4; mt++) {
                mma_f16(accg[mt][0], af[mt], &bg[0]);
                mma_f16(accg[mt][1], af[mt], &bg[2]);
                mma_f16(accu[mt][0], af[mt], &bu[0]);
                mma_f16(accu[mt][1], af[mt], &bu[2]);
            }
        }
    }

    // epilogue: silu(g)*u -> fp16 store
#pragma unroll
    for (int mt = 0; mt < 4; mt++) {
        int r0 = m0 + wm*64 + mt*16 + g;
        __half* row0 = g_hh + ((size_t)e*SLOTS_PER_E + r0) * FDIM;
        __half* row1 = g_hh + ((size_t)e*SLOTS_PER_E + r0 + 8) * FDIM;
#pragma unroll
        for (int nt = 0; nt < 2; nt++) {
            int c0 = n0 + wn*16 + nt*8 + tg*2;
            float2 v0, v1;
            v0.x = silu_mul(accg[mt][nt][0], accu[mt][nt][0]);
            v0.y = silu_mul(accg[mt][nt][1], accu[mt][nt][1]);
            v1.x = silu_mul(accg[mt][nt][2], accu[mt][nt][2]);
            v1.y = silu_mul(accg[mt][nt][3], accu[mt][nt][3]);
            *(__half2*)(row0 + c0) = __float22half2_rn(v0);
            *(__half2*)(row1 + c0) = __float22half2_rn(v1);
        }
    }
}

// ---------------- GEMM2 (fp16 mma + ldmatrix), per-expert, 256x128 tile — atomic accumulate ----------------
// grid: (DDIM/128, SLOTS_PER_E/256), block 512, dyn smem
__global__ void __launch_bounds__(512, 1) gemm2_h(float* __restrict__ out, int e)
{
    int m0 = blockIdx.y * 256;
    int seg = (m0 >= CAP) ? 1 : 0;
    int lim = min(g_cnt[seg*NEXP + e], CAP);
    if ((m0 - seg*CAP) >= lim) return;

    int n0 = blockIdx.x * 128;

    extern __shared__ __half smh[];
    unsigned smu = (unsigned)__cvta_generic_to_shared(smh);

    int tid = threadIdx.x;
    int ar = tid >> 1;
    int hc = (tid & 1) * 16;
    const __half* ap = g_hh + ((size_t)e*SLOTS_PER_E + m0 + ar) * FDIM + hc;
    int br = tid >> 2;
    int bo = (tid & 3) * 8;
    const __half* bp = g_woh + ((size_t)e*DDIM + n0 + br) * FDIM + bo;

    const int KT = FDIM / BKH;           // 128

#pragma unroll
    for (int s = 0; s < STAGES-1; s++) {
        __half* sA = smh + s*STG_H + ar*HSTRIDE + hc;
        __half* sB = smh + s*STG_H + ASTG + br*HSTRIDE + bo;
        int k0 = s * BKH;
        cp_async16(sA,     ap + k0,     16);
        cp_async16(sA + 8, ap + k0 + 8, 16);
        cp_async16(sB,     bp + k0,     16);
        cp_commit();
    }

    float acc[4][4][4];
#pragma unroll
    for (int a = 0; a < 4; a++)
#pragma unroll
        for (int b = 0; b < 4; b++)
#pragma unroll
            for (int c = 0; c < 4; c++) acc[a][b][c] = 0.f;

    int wid = tid >> 5, lane = tid & 31;
    int wm = wid & 3, wn = wid >> 2;      // 4 m-warps(64 rows) x 4 n-warps(32 cols)
    int g = lane >> 2, tg = lane & 3;
    int l8 = lane & 7, g1 = lane >> 3;

    unsigned aoff[4];
#pragma unroll
    for (int mt = 0; mt < 4; mt++)
        aoff[mt] = ((wm*64 + mt*16 + (g1 & 1)*8 + l8) * HSTRIDE + (g1 >> 1)*8) * 2;
    unsigned boff[2];
#pragma unroll
    for (int p = 0; p < 2; p++)
        boff[p] = ((wn*32 + p*16 + (g1 >> 1)*8 + l8) * HSTRIDE + (g1 & 1)*8) * 2 + ASTG*2;

    for (int kt = 0; kt < KT; kt++) {
        cp_wait();
        __syncthreads();
        int pf = kt + STAGES - 1;
        if (pf < KT) {
            int st = pf % STAGES;
            __half* sA = smh + st*STG_H + ar*HSTRIDE + hc;
            __half* sB = smh + st*STG_H + ASTG + br*HSTRIDE + bo;
            int k0 = pf * BKH;
            cp_async16(sA,     ap + k0,     16);
            cp_async16(sA + 8, ap + k0 + 8, 16);
            cp_async16(sB,     bp + k0,     16);
        }
        cp_commit();
        unsigned stOff = smu + (kt % STAGES)*(STG_H*2);
#pragma unroll
        for (int kk = 0; kk < 2; kk++) {
            unsigned kb = kk * 32;
            unsigned af[4][4], b2[2][4];
#pragma unroll
            for (int mt = 0; mt < 4; mt++) ldsm_x4(af[mt], stOff + aoff[mt] + kb);
#pragma unroll
            for (int p = 0; p < 2; p++) ldsm_x4(b2[p], stOff + boff[p] + kb);
#pragma unroll
            for (int mt = 0; mt < 4; mt++)
#pragma unroll
                for (int p = 0; p < 2; p++) {
                    mma_f16(acc[mt][2*p+0], af[mt], &b2[p][0]);
                    mma_f16(acc[mt][2*p+1], af[mt], &b2[p][2]);
                }
        }
    }

    // epilogue: scaled atomic accumulate directly into out
#pragma unroll
    for (int mt = 0; mt < 4; mt++) {
        int r0 = m0 + wm*64 + mt*16 + g;
        int slot0 = e*SLOTS_PER_E + r0;
        int t0 = g_tok[slot0];
        int t1 = g_tok[slot0 + 8];
        float w0 = g_wgt[slot0];
        float w1 = g_wgt[slot0 + 8];
        float* o0 = out + (size_t)max(t0, 0) * DDIM;
        float* o1 = out + (size_t)max(t1, 0) * DDIM;
#pragma unroll
        for (int nt = 0; nt < 4; nt++) {
            int c0 = n0 + wn*32 + nt*8 + tg*2;
            if (t0 >= 0) {
                atomicAdd(o0 + c0,     acc[mt][nt][0]*w0);
                atomicAdd(o0 + c0 + 1, acc[mt][nt][1]*w0);
            }
            if (t1 >= 0) {
                atomicAdd(o1 + c0,     acc[mt][nt][2]*w1);
                atomicAdd(o1 + c0 + 1, acc[mt][nt][3]*w1);
            }
        }
    }
}

// ---------------- aux loss: deterministic tree reduction ----------------
__global__ void __launch_bounds__(1024) aux_kernel(float* __restrict__ out_aux)
{
    __shared__ float sb[1024];
    __shared__ float res[9];
    int tid = threadIdx.x;
    float pacc[NEXP];
#pragma unroll
    for (int e = 0; e < NEXP; e++) pacc[e] = 0.f;
    float zacc = 0.f;
    for (int i = 0; i < N_TOK/1024; i++) {
        int t = tid * (N_TOK/1024) + i;
        const float* pr = g_probs + (size_t)t * NEXP;
#pragma unroll
        for (int e = 0; e < NEXP; e++) pacc[e] += pr[e];
        float l = g_lse[t];
        zacc += l * l;
    }
    for (int e = 0; e < NEXP; e++) {
        sb[tid] = pacc[e];
        __syncthreads();
        for (int s = 512; s > 0; s >>= 1) {
            if (tid < s) sb[tid] += sb[tid + s];
            __syncthreads();
        }
        if (tid == 0) res[e] = sb[0];
        __syncthreads();
    }
    sb[tid] = zacc;
    __syncthreads();
    for (int s = 512; s > 0; s >>= 1) {
        if (tid < s) sb[tid] += sb[tid + s];
        __syncthreads();
    }
    if (tid == 0) res[8] = sb[0];
    __syncthreads();
    if (tid == 0) {
        float lb = 0.f;
#pragma unroll
        for (int e = 0; e < NEXP; e++) {
            float density = (float)(g_cnt[e] + g_cnt[NEXP + e]) / (float)(N_TOK * 2);
            float mean_p = res[e] / (float)N_TOK;
            lb += density * mean_p;
        }
        lb *= 0.01f * (float)NEXP;
        float z = 0.001f * (res[8] / (float)N_TOK);
        out_aux[0] = lb + z;
    }
}

// ---------------- launch (fork-join: per-expert gemm1 -> gemm2 cross-stream pipeline) ----------------
extern "C" void kernel_launch(void* const* d_in, const int* in_sizes, int n_in,
                              void* d_out, int out_size)
{
    const float* x       = (const float*)d_in[0];
    const float* gate_w  = (const float*)d_in[1];
    const float* wi_gate = (const float*)d_in[2];
    const float* wi_up   = (const float*)d_in[3];
    const float* wo      = (const float*)d_in[4];
    float* out = (float*)d_out;

    static bool s_init = false;
    static cudaStream_t s2;
    static cudaEvent_t evRoot, evW[NEXP], evG1[NEXP], evR, evC;
    if (!s_init) {
        cudaFuncSetAttribute(gemm1_h, cudaFuncAttributeMaxDynamicSharedMemorySize, SMEM_BYTES);
        cudaFuncSetAttribute(gemm2_h, cudaFuncAttributeMaxDynamicSharedMemorySize, SMEM_BYTES);
        cudaStreamCreateWithFlags(&s2, cudaStreamNonBlocking);
        cudaEventCreateWithFlags(&evRoot, cudaEventDisableTiming);
        for (int e = 0; e < NEXP; e++) {
            cudaEventCreateWithFlags(&evW[e],  cudaEventDisableTiming);
            cudaEventCreateWithFlags(&evG1[e], cudaEventDisableTiming);
        }
        cudaEventCreateWithFlags(&evR, cudaEventDisableTiming);
        cudaEventCreateWithFlags(&evC, cudaEventDisableTiming);
        s_init = true;
    }

    // fork
    cudaEventRecord(evRoot, 0);
    cudaStreamWaitEvent(s2, evRoot, 0);

    // s2: x convert, per-expert weight converts, wo convert, out zero
    conv_x<<<512, 256, 0, s2>>>((const float2*)x);
    for (int e = 0; e < NEXP; e++) {
        conv_wgu_e<<<1024, 256, 0, s2>>>((const float2*)wi_gate, (const float2*)wi_up, e);
        cudaEventRecord(evW[e], s2);
    }
    conv_wo<<<1024, 256, 0, s2>>>((const float2*)wo);
    zero_out_kernel<<<(N_TOK*DDIM/4)/256, 256, 0, s2>>>((float4*)out);

    // main: routing
    router_kernel<<<N_TOK, 256>>>(x, gate_w);
    rank_build_kernel<<<16, 1024>>>();
    cudaEventRecord(evR, 0);

    // s2: aux loss (needs probs/lse/cnt only), overlapped with GEMMs
    if (out_size > N_TOK * DDIM) {
        cudaStreamWaitEvent(s2, evR, 0);
        aux_kernel<<<1, 1024, 0, s2>>>(out + (size_t)N_TOK * DDIM);
    }

    // main: per-expert gemm1; s2: per-expert gemm2 chained on gemm1(e)
    for (int e = 0; e < NEXP; e++) {
        cudaStreamWaitEvent(0, evW[e], 0);
        gemm1_h<<<dim3(FDIM/64, SLOTS_PER_E/256), 512, SMEM_BYTES>>>(e);
        cudaEventRecord(evG1[e], 0);
        cudaStreamWaitEvent(s2, evG1[e], 0);
        gemm2_h<<<dim3(DDIM/128, SLOTS_PER_E/256), 512, SMEM_BYTES, s2>>>(out, e);
    }
    cudaEventRecord(evC, s2);

    // join side stream back (gemm2 chain + aux) before capture ends
    cudaStreamWaitEvent(0, evC, 0);
}

// round 15
// speedup vs baseline: 1.1106x; 1.1106x over previous
#include <cuda_runtime.h>
#include <cuda_fp16.h>
#include <cstdint>
#include <math.h>

// Problem constants
#define N_TOK   8192
#define DDIM    1024
#define FDIM    4096
#define NEXP    8
#define CAP     1280          // int(8192/8 * 1.25)
#define SLOTS_PER_E (2*CAP)   // 2560
#define TOT_SLOTS (NEXP*SLOTS_PER_E)

// fp16 GEMM tiling: R7 config (best mainloop)
#define STAGES  4
#define BKH     32                  // halves per K-chunk
#define HSTRIDE 40                  // halves per smem row (32 + 8 pad -> 80B)
#define A_ROWS  256
#define B_ROWS  128
#define ASTG    (A_ROWS*HSTRIDE)
#define BSTG    (B_ROWS*HSTRIDE)
#define STG_H   (ASTG+BSTG)
#define SMEM_BYTES (STAGES*STG_H*2) // 122880

// ---------------- scratch (static __device__, no runtime allocs) ----------------
__device__ __half g_xh[(size_t)N_TOK*DDIM];             // fp16 x
__device__ __half g_wgh[(size_t)NEXP*FDIM*DDIM];        // fp16 wi_gate
__device__ __half g_wuh[(size_t)NEXP*FDIM*DDIM];        // fp16 wi_up
__device__ __half g_woh[(size_t)NEXP*DDIM*FDIM];        // fp16 wo
__device__ __half g_hh[(size_t)NEXP*SLOTS_PER_E*FDIM];  // fp16 fused activation
__device__ int   g_tok[TOT_SLOTS];
__device__ float g_wgt[TOT_SLOTS];
__device__ int   g_eids[N_TOK*2];
__device__ float g_ew[N_TOK*2];
__device__ float g_probs[N_TOK*NEXP];
__device__ float g_lse[N_TOK];
__device__ int   g_cnt[2*NEXP];

// ---------------- helpers ----------------
__device__ __forceinline__ void cp_async16(void* dst, const void* src, int bytes)
{
    unsigned s = (unsigned)__cvta_generic_to_shared(dst);
    asm volatile("cp.async.ca.shared.global [%0], [%1], 16, %2;\n"
                 :: "r"(s), "l"(src), "r"(bytes));
}
__device__ __forceinline__ void cp_commit() { asm volatile("cp.async.commit_group;\n"); }
__device__ __forceinline__ void cp_wait()   { asm volatile("cp.async.wait_group %0;\n" :: "n"(STAGES-2)); }

__device__ __forceinline__ void mma_f16(float* c, const unsigned* a, const unsigned* b)
{
    asm volatile(
        "mma.sync.aligned.m16n8k16.row.col.f32.f16.f16.f32 "
        "{%0,%1,%2,%3}, {%4,%5,%6,%7}, {%8,%9}, {%0,%1,%2,%3};\n"
        : "+f"(c[0]), "+f"(c[1]), "+f"(c[2]), "+f"(c[3])
        : "r"(a[0]), "r"(a[1]), "r"(a[2]), "r"(a[3]), "r"(b[0]), "r"(b[1]));
}

__device__ __forceinline__ void ldsm_x4(unsigned* r, unsigned addr)
{
    asm volatile("ldmatrix.sync.aligned.m8n8.x4.shared.b16 {%0,%1,%2,%3}, [%4];"
                 : "=r"(r[0]), "=r"(r[1]), "=r"(r[2]), "=r"(r[3]) : "r"(addr));
}

__device__ __forceinline__ float silu_mul(float g, float u)
{
    return g / (1.f + expf(-g)) * u;
}

// vector atomic add (sm_90+): one RED for a contiguous float pair
__device__ __forceinline__ void red_add_v2(float* p, float a, float b)
{
    asm volatile("red.global.add.v2.f32 [%0], {%1, %2};"
                 :: "l"(p), "f"(a), "f"(b) : "memory");
}

// ---------------- fp32 -> fp16 converts (pipelined per expert) ----------------
#define NX2 (N_TOK*DDIM/2)
#define NW2 (NEXP*FDIM*DDIM/2)
#define NWE2 (FDIM*DDIM/2)        // one expert's wg (or wu) slice in half2 units

__global__ void __launch_bounds__(256) conv_x(const float2* __restrict__ x)
{
    int stride = gridDim.x * blockDim.x;
    for (int i = blockIdx.x*blockDim.x + threadIdx.x; i < NX2; i += stride)
        ((__half2*)g_xh)[i] = __float22half2_rn(x[i]);
}

__global__ void __launch_bounds__(256) conv_wgu_e(const float2* __restrict__ wg,
                                                  const float2* __restrict__ wu,
                                                  int e)
{
    size_t base = (size_t)e * NWE2;
    int stride = gridDim.x * blockDim.x;
    for (int i = blockIdx.x*blockDim.x + threadIdx.x; i < NWE2; i += stride) {
        ((__half2*)g_wgh)[base + i] = __float22half2_rn(wg[base + i]);
        ((__half2*)g_wuh)[base + i] = __float22half2_rn(wu[base + i]);
    }
}

__global__ void __launch_bounds__(256) conv_wo(const float2* __restrict__ wo)
{
    long long stride = (long long)gridDim.x * blockDim.x;
    for (long long i = (long long)blockIdx.x*blockDim.x + threadIdx.x; i < NW2; i += stride)
        ((__half2*)g_woh)[i] = __float22half2_rn(wo[i]);
}

// ---------------- zero output (atomic accumulate base) ----------------
__global__ void __launch_bounds__(256) zero_out_kernel(float4* __restrict__ out4)
{
    int i = blockIdx.x * 256 + threadIdx.x;
    out4[i] = make_float4(0.f, 0.f, 0.f, 0.f);
}

// ---------------- router: logits, softmax, top-2, weights ----------------
__global__ void __launch_bounds__(256) router_kernel(const float* __restrict__ x,
                                                     const float* __restrict__ gw)
{
    int t = blockIdx.x;
    const float* xr = x + (size_t)t * DDIM;
    __shared__ float sred[NEXP][256];
    float acc[NEXP];
#pragma unroll
    for (int e = 0; e < NEXP; e++) acc[e] = 0.f;
    for (int d = threadIdx.x; d < DDIM; d += 256) {
        float xv = xr[d];
#pragma unroll
        for (int e = 0; e < NEXP; e++) acc[e] += xv * gw[e*DDIM + d];
    }
#pragma unroll
    for (int e = 0; e < NEXP; e++) sred[e][threadIdx.x] = acc[e];
    __syncthreads();
    for (int s = 128; s > 0; s >>= 1) {
        if (threadIdx.x < s) {
#pragma unroll
            for (int e = 0; e < NEXP; e++) sred[e][threadIdx.x] += sred[e][threadIdx.x + s];
        }
        __syncthreads();
    }
    if (threadIdx.x == 0) {
        float lg[NEXP];
#pragma unroll
        for (int e = 0; e < NEXP; e++) lg[e] = sred[e][0];
        float mx = lg[0];
#pragma unroll
        for (int e = 1; e < NEXP; e++) mx = fmaxf(mx, lg[e]);
        float se = 0.f, p[NEXP];
#pragma unroll
        for (int e = 0; e < NEXP; e++) { p[e] = expf(lg[e] - mx); se += p[e]; }
        float inv = 1.f / se;
#pragma unroll
        for (int e = 0; e < NEXP; e++) { p[e] *= inv; g_probs[t*NEXP + e] = p[e]; }
        g_lse[t] = mx + logf(se);
        int i0 = 0;
#pragma unroll
        for (int e = 1; e < NEXP; e++) if (p[e] > p[i0]) i0 = e;
        int i1 = -1;
#pragma unroll
        for (int e = 0; e < NEXP; e++) {
            if (e == i0) continue;
            if (i1 < 0 || p[e] > p[i1]) i1 = e;
        }
        float s2 = p[i0] + p[i1];
        g_eids[t*2 + 0] = i0; g_eids[t*2 + 1] = i1;
        g_ew[t*2 + 0] = p[i0] / s2; g_ew[t*2 + 1] = p[i1] / s2;
    }
}

// ---------------- rank + clear + build fused (1024 threads, shfl-scan) ----------------
__global__ void __launch_bounds__(1024) rank_build_kernel()
{
    int k = blockIdx.x >> 3;
    int e = blockIdx.x & 7;
    int segbase = e*SLOTS_PER_E + k*CAP;
    int tid = threadIdx.x;
    for (int i = tid; i < CAP; i += 1024) {
        g_tok[segbase + i] = -1;
        g_wgt[segbase + i] = 0.f;
    }

    __shared__ int warp_sums[32];
    __shared__ int s_base;
    if (tid == 0) s_base = 0;
    __syncthreads();
    int lane = tid & 31, wid = tid >> 5;
    for (int c = 0; c < N_TOK; c += 1024) {
        int t = c + tid;
        int flag = (g_eids[t*2 + k] == e) ? 1 : 0;
        unsigned m = __ballot_sync(0xffffffffu, flag);
        int pre = __popc(m & ((1u << lane) - 1u));
        if (lane == 31) warp_sums[wid] = pre + flag;
        __syncthreads();
        if (wid == 0) {
            int v = warp_sums[lane];
#pragma unroll
            for (int o = 1; o < 32; o <<= 1) {
                int n = __shfl_up_sync(0xffffffffu, v, o);
                if (lane >= o) v += n;
            }
            warp_sums[lane] = v;   // inclusive scan
        }
        __syncthreads();
        int wbase = s_base + (wid ? warp_sums[wid-1] : 0);
        if (flag) {
            int r = wbase + pre;
            if (r < CAP) {
                g_tok[segbase + r] = t;
                g_wgt[segbase + r] = g_ew[t*2 + k];
            }
        }
        __syncthreads();
        if (tid == 0) s_base += warp_sums[31];
        __syncthreads();
    }
    if (tid == 0) g_cnt[k*NEXP + e] = s_base;
}

// ---------------- fused GEMM1 (fp16 mma + ldmatrix), per-expert, 256x(64+64) tile ----------------
// grid: (FDIM/64, SLOTS_PER_E/256), block 512, dyn smem
__global__ void __launch_bounds__(512, 1) gemm1_h(int e)
{
    int m0 = blockIdx.y * 256;
    int seg = (m0 >= CAP) ? 1 : 0;
    int lim = min(g_cnt[seg*NEXP + e], CAP);
    if ((m0 - seg*CAP) >= lim) return;

    int n0 = blockIdx.x * 64;

    extern __shared__ __half smh[];
    unsigned smu = (unsigned)__cvta_generic_to_shared(smh);

    int tid = threadIdx.x;
    int ar = tid >> 1;
    int hc = (tid & 1) * 16;
    int tok = g_tok[e*SLOTS_PER_E + m0 + ar];
    const __half* ap = g_xh + (size_t)max(tok, 0) * DDIM + hc;
    int abytes = (tok >= 0) ? 16 : 0;
    int br = tid >> 2;
    int bo = (tid & 3) * 8;
    const __half* bp = (br < 64)
        ? (g_wgh + ((size_t)e*FDIM + n0 + br) * DDIM + bo)
        : (g_wuh + ((size_t)e*FDIM + n0 + (br - 64)) * DDIM + bo);

    const int KT = DDIM / BKH;           // 32

#pragma unroll
    for (int s = 0; s < STAGES-1; s++) {
        __half* sA = smh + s*STG_H + ar*HSTRIDE + hc;
        __half* sB = smh + s*STG_H + ASTG + br*HSTRIDE + bo;
        int k0 = s * BKH;
        cp_async16(sA,      ap + k0,      abytes);
        cp_async16(sA + 8,  ap + k0 + 8,  abytes);
        cp_async16(sB,      bp + k0,      16);
        cp_commit();
    }

    float accg[4][2][4], accu[4][2][4];
#pragma unroll
    for (int a = 0; a < 4; a++)
#pragma unroll
        for (int b = 0; b < 2; b++)
#pragma unroll
            for (int c = 0; c < 4; c++) { accg[a][b][c] = 0.f; accu[a][b][c] = 0.f; }

    int wid = tid >> 5, lane = tid & 31;
    int wm = wid & 3, wn = wid >> 2;      // 4 m-warps(64 rows) x 4 n-warps(16 cols)
    int g = lane >> 2, tg = lane & 3;
    int l8 = lane & 7, g1 = lane >> 3;

    unsigned aoff[4];
#pragma unroll
    for (int mt = 0; mt < 4; mt++)
        aoff[mt] = ((wm*64 + mt*16 + (g1 & 1)*8 + l8) * HSTRIDE + (g1 >> 1)*8) * 2;
    unsigned bgoff = ((wn*16 + (g1 >> 1)*8 + l8) * HSTRIDE + (g1 & 1)*8) * 2 + ASTG*2;
    unsigned buoff = ((64 + wn*16 + (g1 >> 1)*8 + l8) * HSTRIDE + (g1 & 1)*8) * 2 + ASTG*2;

    for (int kt = 0; kt < KT; kt++) {
        cp_wait();
        __syncthreads();
        int pf = kt + STAGES - 1;
        if (pf < KT) {
            int st = pf % STAGES;
            __half* sA = smh + st*STG_H + ar*HSTRIDE + hc;
            __half* sB = smh + st*STG_H + ASTG + br*HSTRIDE + bo;
            int k0 = pf * BKH;
            cp_async16(sA,      ap + k0,      abytes);
            cp_async16(sA + 8,  ap + k0 + 8,  abytes);
            cp_async16(sB,      bp + k0,      16);
        }
        cp_commit();
        unsigned stOff = smu + (kt % STAGES)*(STG_H*2);
#pragma unroll
        for (int kk = 0; kk < 2; kk++) {
            unsigned kb = kk * 32;
            unsigned af[4][4], bg[4], bu[4];
#pragma unroll
            for (int mt = 0; mt < 4; mt++) ldsm_x4(af[mt], stOff + aoff[mt] + kb);
            ldsm_x4(bg, stOff + bgoff + kb);
            ldsm_x4(bu, stOff + buoff + kb);
#pragma unroll
            for (int mt = 0; mt < 4; mt++) {
                mma_f16(accg[mt][0], af[mt], &bg[0]);
                mma_f16(accg[mt][1], af[mt], &bg[2]);
                mma_f16(accu[mt][0], af[mt], &bu[0]);
                mma_f16(accu[mt][1], af[mt], &bu[2]);
            }
        }
    }

    // epilogue: silu(g)*u -> fp16 store
#pragma unroll
    for (int mt = 0; mt < 4; mt++) {
        int r0 = m0 + wm*64 + mt*16 + g;
        __half* row0 = g_hh + ((size_t)e*SLOTS_PER_E + r0) * FDIM;
        __half* row1 = g_hh + ((size_t)e*SLOTS_PER_E + r0 + 8) * FDIM;
#pragma unroll
        for (int nt = 0; nt < 2; nt++) {
            int c0 = n0 + wn*16 + nt*8 + tg*2;
            float2 v0, v1;
            v0.x = silu_mul(accg[mt][nt][0], accu[mt][nt][0]);
            v0.y = silu_mul(accg[mt][nt][1], accu[mt][nt][1]);
            v1.x = silu_mul(accg[mt][nt][2], accu[mt][nt][2]);
            v1.y = silu_mul(accg[mt][nt][3], accu[mt][nt][3]);
            *(__half2*)(row0 + c0) = __float22half2_rn(v0);
            *(__half2*)(row1 + c0) = __float22half2_rn(v1);
        }
    }
}

// ---------------- GEMM2 (fp16 mma + ldmatrix), 256x128 tile — vector-red accumulate ----------------
// grid: (DDIM/128, SLOTS_PER_E/256, NEXP), block 512, dyn smem
__global__ void __launch_bounds__(512, 1) gemm2_h(float* __restrict__ out)
{
    int e = blockIdx.z;
    int m0 = blockIdx.y * 256;
    int seg = (m0 >= CAP) ? 1 : 0;
    int lim = min(g_cnt[seg*NEXP + e], CAP);
    if ((m0 - seg*CAP) >= lim) return;

    int n0 = blockIdx.x * 128;

    extern __shared__ __half smh[];
    unsigned smu = (unsigned)__cvta_generic_to_shared(smh);

    int tid = threadIdx.x;
    int ar = tid >> 1;
    int hc = (tid & 1) * 16;
    const __half* ap = g_hh + ((size_t)e*SLOTS_PER_E + m0 + ar) * FDIM + hc;
    int br = tid >> 2;
    int bo = (tid & 3) * 8;
    const __half* bp = g_woh + ((size_t)e*DDIM + n0 + br) * FDIM + bo;

    const int KT = FDIM / BKH;           // 128

#pragma unroll
    for (int s = 0; s < STAGES-1; s++) {
        __half* sA = smh + s*STG_H + ar*HSTRIDE + hc;
        __half* sB = smh + s*STG_H + ASTG + br*HSTRIDE + bo;
        int k0 = s * BKH;
        cp_async16(sA,     ap + k0,     16);
        cp_async16(sA + 8, ap + k0 + 8, 16);
        cp_async16(sB,     bp + k0,     16);
        cp_commit();
    }

    float acc[4][4][4];
#pragma unroll
    for (int a = 0; a < 4; a++)
#pragma unroll
        for (int b = 0; b < 4; b++)
#pragma unroll
            for (int c = 0; c < 4; c++) acc[a][b][c] = 0.f;

    int wid = tid >> 5, lane = tid & 31;
    int wm = wid & 3, wn = wid >> 2;      // 4 m-warps(64 rows) x 4 n-warps(32 cols)
    int g = lane >> 2, tg = lane & 3;
    int l8 = lane & 7, g1 = lane >> 3;

    unsigned aoff[4];
#pragma unroll
    for (int mt = 0; mt < 4; mt++)
        aoff[mt] = ((wm*64 + mt*16 + (g1 & 1)*8 + l8) * HSTRIDE + (g1 >> 1)*8) * 2;
    unsigned boff[2];
#pragma unroll
    for (int p = 0; p < 2; p++)
        boff[p] = ((wn*32 + p*16 + (g1 >> 1)*8 + l8) * HSTRIDE + (g1 & 1)*8) * 2 + ASTG*2;

    for (int kt = 0; kt < KT; kt++) {
        cp_wait();
        __syncthreads();
        int pf = kt + STAGES - 1;
        if (pf < KT) {
            int st = pf % STAGES;
            __half* sA = smh + st*STG_H + ar*HSTRIDE + hc;
            __half* sB = smh + st*STG_H + ASTG + br*HSTRIDE + bo;
            int k0 = pf * BKH;
            cp_async16(sA,     ap + k0,     16);
            cp_async16(sA + 8, ap + k0 + 8, 16);
            cp_async16(sB,     bp + k0,     16);
        }
        cp_commit();
        unsigned stOff = smu + (kt % STAGES)*(STG_H*2);
#pragma unroll
        for (int kk = 0; kk < 2; kk++) {
            unsigned kb = kk * 32;
            unsigned af[4][4], b2[2][4];
#pragma unroll
            for (int mt = 0; mt < 4; mt++) ldsm_x4(af[mt], stOff + aoff[mt] + kb);
#pragma unroll
            for (int p = 0; p < 2; p++) ldsm_x4(b2[p], stOff + boff[p] + kb);
#pragma unroll
            for (int mt = 0; mt < 4; mt++)
#pragma unroll
                for (int p = 0; p < 2; p++) {
                    mma_f16(acc[mt][2*p+0], af[mt], &b2[p][0]);
                    mma_f16(acc[mt][2*p+1], af[mt], &b2[p][2]);
                }
        }
    }

    // epilogue: scaled vector-red accumulate directly into out
    // (<=2 contributions per element, fp add commutative -> deterministic)
#pragma unroll
    for (int mt = 0; mt < 4; mt++) {
        int r0 = m0 + wm*64 + mt*16 + g;
        int slot0 = e*SLOTS_PER_E + r0;
        int t0 = g_tok[slot0];
        int t1 = g_tok[slot0 + 8];
        float w0 = g_wgt[slot0];
        float w1 = g_wgt[slot0 + 8];
        float* o0 = out + (size_t)max(t0, 0) * DDIM;
        float* o1 = out + (size_t)max(t1, 0) * DDIM;
#pragma unroll
        for (int nt = 0; nt < 4; nt++) {
            int c0 = n0 + wn*32 + nt*8 + tg*2;
            if (t0 >= 0) red_add_v2(o0 + c0, acc[mt][nt][0]*w0, acc[mt][nt][1]*w0);
            if (t1 >= 0) red_add_v2(o1 + c0, acc[mt][nt][2]*w1, acc[mt][nt][3]*w1);
        }
    }
}

// ---------------- aux loss: deterministic tree reduction ----------------
__global__ void __launch_bounds__(1024) aux_kernel(float* __restrict__ out_aux)
{
    __shared__ float sb[1024];
    __shared__ float res[9];
    int tid = threadIdx.x;
    float pacc[NEXP];
#pragma unroll
    for (int e = 0; e < NEXP; e++) pacc[e] = 0.f;
    float zacc = 0.f;
    for (int i = 0; i < N_TOK/1024; i++) {
        int t = tid * (N_TOK/1024) + i;
        const float* pr = g_probs + (size_t)t * NEXP;
#pragma unroll
        for (int e = 0; e < NEXP; e++) pacc[e] += pr[e];
        float l = g_lse[t];
        zacc += l * l;
    }
    for (int e = 0; e < NEXP; e++) {
        sb[tid] = pacc[e];
        __syncthreads();
        for (int s = 512; s > 0; s >>= 1) {
            if (tid < s) sb[tid] += sb[tid + s];
            __syncthreads();
        }
        if (tid == 0) res[e] = sb[0];
        __syncthreads();
    }
    sb[tid] = zacc;
    __syncthreads();
    for (int s = 512; s > 0; s >>= 1) {
        if (tid < s) sb[tid] += sb[tid + s];
        __syncthreads();
    }
    if (tid == 0) res[8] = sb[0];
    __syncthreads();
    if (tid == 0) {
        float lb = 0.f;
#pragma unroll
        for (int e = 0; e < NEXP; e++) {
            float density = (float)(g_cnt[e] + g_cnt[NEXP + e]) / (float)(N_TOK * 2);
            float mean_p = res[e] / (float)N_TOK;
            lb += density * mean_p;
        }
        lb *= 0.01f * (float)NEXP;
        float z = 0.001f * (res[8] / (float)N_TOK);
        out_aux[0] = lb + z;
    }
}

// ---------------- launch (R13 schedule: pipelined converts + aux on side stream) ----------------
extern "C" void kernel_launch(void* const* d_in, const int* in_sizes, int n_in,
                              void* d_out, int out_size)
{
    const float* x       = (const float*)d_in[0];
    const float* gate_w  = (const float*)d_in[1];
    const float* wi_gate = (const float*)d_in[2];
    const float* wi_up   = (const float*)d_in[3];
    const float* wo      = (const float*)d_in[4];
    float* out = (float*)d_out;

    static bool s_init = false;
    static cudaStream_t s2;
    static cudaEvent_t evRoot, evW[NEXP], evB, evR, evC;
    if (!s_init) {
        cudaFuncSetAttribute(gemm1_h, cudaFuncAttributeMaxDynamicSharedMemorySize, SMEM_BYTES);
        cudaFuncSetAttribute(gemm2_h, cudaFuncAttributeMaxDynamicSharedMemorySize, SMEM_BYTES);
        cudaStreamCreateWithFlags(&s2, cudaStreamNonBlocking);
        cudaEventCreateWithFlags(&evRoot, cudaEventDisableTiming);
        for (int e = 0; e < NEXP; e++) cudaEventCreateWithFlags(&evW[e], cudaEventDisableTiming);
        cudaEventCreateWithFlags(&evB, cudaEventDisableTiming);
        cudaEventCreateWithFlags(&evR, cudaEventDisableTiming);
        cudaEventCreateWithFlags(&evC, cudaEventDisableTiming);
        s_init = true;
    }

    // fork
    cudaEventRecord(evRoot, 0);
    cudaStreamWaitEvent(s2, evRoot, 0);

    // s2: x convert, then per-expert weight converts (event per expert)
    conv_x<<<512, 256, 0, s2>>>((const float2*)x);
    for (int e = 0; e < NEXP; e++) {
        conv_wgu_e<<<1024, 256, 0, s2>>>((const float2*)wi_gate, (const float2*)wi_up, e);
        cudaEventRecord(evW[e], s2);
    }
    conv_wo<<<1024, 256, 0, s2>>>((const float2*)wo);
    zero_out_kernel<<<(N_TOK*DDIM/4)/256, 256, 0, s2>>>((float4*)out);
    cudaEventRecord(evB, s2);

    // main: routing
    router_kernel<<<N_TOK, 256>>>(x, gate_w);
    rank_build_kernel<<<16, 1024>>>();
    cudaEventRecord(evR, 0);

    // s2: aux loss (needs probs/lse/cnt only), overlapped with GEMMs
    if (out_size > N_TOK * DDIM) {
        cudaStreamWaitEvent(s2, evR, 0);
        aux_kernel<<<1, 1024, 0, s2>>>(out + (size_t)N_TOK * DDIM);
    }
    cudaEventRecord(evC, s2);

    // main: per-expert gemm1, each gated only on its own weight conversion
    for (int e = 0; e < NEXP; e++) {
        cudaStreamWaitEvent(0, evW[e], 0);
        gemm1_h<<<dim3(FDIM/64, SLOTS_PER_E/256), 512, SMEM_BYTES>>>(e);
    }

    // gemm2 needs wo halves + zeroed out (hidden under gemm1)
    cudaStreamWaitEvent(0, evB, 0);
    gemm2_h<<<dim3(DDIM/128, SLOTS_PER_E/256, NEXP), 512, SMEM_BYTES>>>(out);

    // join side stream back (aux) before capture ends
    cudaStreamWaitEvent(0, evC, 0);
}

// round 16
// speedup vs baseline: 1.1748x; 1.0578x over previous
#include <cuda_runtime.h>
#include <cuda_fp16.h>
#include <cstdint>
#include <math.h>

// Problem constants
#define N_TOK   8192
#define DDIM    1024
#define FDIM    4096
#define NEXP    8
#define CAP     1280          // int(8192/8 * 1.25)
#define SLOTS_PER_E (2*CAP)   // 2560
#define TOT_SLOTS (NEXP*SLOTS_PER_E)

// fp16 GEMM tiling: R7 config (best mainloop)
#define STAGES  4
#define BKH     32                  // halves per K-chunk
#define HSTRIDE 40                  // halves per smem row (32 + 8 pad -> 80B)
#define A_ROWS  256
#define B_ROWS  128
#define ASTG    (A_ROWS*HSTRIDE)
#define BSTG    (B_ROWS*HSTRIDE)
#define STG_H   (ASTG+BSTG)
#define SMEM_BYTES (STAGES*STG_H*2) // 122880

// ---------------- scratch (static __device__, no runtime allocs) ----------------
__device__ __half g_xh[(size_t)N_TOK*DDIM];             // fp16 x
__device__ __half g_wgh[(size_t)NEXP*FDIM*DDIM];        // fp16 wi_gate
__device__ __half g_wuh[(size_t)NEXP*FDIM*DDIM];        // fp16 wi_up
__device__ __half g_woh[(size_t)NEXP*DDIM*FDIM];        // fp16 wo
__device__ __half g_hh[(size_t)NEXP*SLOTS_PER_E*FDIM];  // fp16 fused activation
__device__ int   g_tok[TOT_SLOTS];
__device__ float g_wgt[TOT_SLOTS];
__device__ int   g_eids[N_TOK*2];
__device__ float g_ew[N_TOK*2];
__device__ float g_probs[N_TOK*NEXP];
__device__ float g_lse[N_TOK];
__device__ int   g_cnt[2*NEXP];

// ---------------- helpers ----------------
__device__ __forceinline__ void cp_async16(void* dst, const void* src, int bytes)
{
    unsigned s = (unsigned)__cvta_generic_to_shared(dst);
    asm volatile("cp.async.ca.shared.global [%0], [%1], 16, %2;\n"
                 :: "r"(s), "l"(src), "r"(bytes));
}
__device__ __forceinline__ void cp_commit() { asm volatile("cp.async.commit_group;\n"); }
__device__ __forceinline__ void cp_wait()   { asm volatile("cp.async.wait_group %0;\n" :: "n"(STAGES-2)); }

__device__ __forceinline__ void mma_f16(float* c, const unsigned* a, const unsigned* b)
{
    asm volatile(
        "mma.sync.aligned.m16n8k16.row.col.f32.f16.f16.f32 "
        "{%0,%1,%2,%3}, {%4,%5,%6,%7}, {%8,%9}, {%0,%1,%2,%3};\n"
        : "+f"(c[0]), "+f"(c[1]), "+f"(c[2]), "+f"(c[3])
        : "r"(a[0]), "r"(a[1]), "r"(a[2]), "r"(a[3]), "r"(b[0]), "r"(b[1]));
}

__device__ __forceinline__ void ldsm_x4(unsigned* r, unsigned addr)
{
    asm volatile("ldmatrix.sync.aligned.m8n8.x4.shared.b16 {%0,%1,%2,%3}, [%4];"
                 : "=r"(r[0]), "=r"(r[1]), "=r"(r[2]), "=r"(r[3]) : "r"(addr));
}

__device__ __forceinline__ float silu_mul(float g, float u)
{
    return g / (1.f + expf(-g)) * u;
}

// vector atomic add (sm_90+): one RED for a contiguous float pair
__device__ __forceinline__ void red_add_v2(float* p, float a, float b)
{
    asm volatile("red.global.add.v2.f32 [%0], {%1, %2};"
                 :: "l"(p), "f"(a), "f"(b) : "memory");
}

// ---------------- fp32 -> fp16 converts (pipelined per expert) ----------------
#define NX2 (N_TOK*DDIM/2)
#define NW2 (NEXP*FDIM*DDIM/2)
#define NWE2 (FDIM*DDIM/2)        // one expert's wg (or wu) slice in half2 units

__global__ void __launch_bounds__(256) conv_x(const float2* __restrict__ x)
{
    int stride = gridDim.x * blockDim.x;
    for (int i = blockIdx.x*blockDim.x + threadIdx.x; i < NX2; i += stride)
        ((__half2*)g_xh)[i] = __float22half2_rn(x[i]);
}

__global__ void __launch_bounds__(256) conv_wgu_e(const float2* __restrict__ wg,
                                                  const float2* __restrict__ wu,
                                                  int e)
{
    size_t base = (size_t)e * NWE2;
    int stride = gridDim.x * blockDim.x;
    for (int i = blockIdx.x*blockDim.x + threadIdx.x; i < NWE2; i += stride) {
        ((__half2*)g_wgh)[base + i] = __float22half2_rn(wg[base + i]);
        ((__half2*)g_wuh)[base + i] = __float22half2_rn(wu[base + i]);
    }
}

__global__ void __launch_bounds__(256) conv_wo(const float2* __restrict__ wo)
{
    long long stride = (long long)gridDim.x * blockDim.x;
    for (long long i = (long long)blockIdx.x*blockDim.x + threadIdx.x; i < NW2; i += stride)
        ((__half2*)g_woh)[i] = __float22half2_rn(wo[i]);
}

// ---------------- zero output (atomic accumulate base) ----------------
__global__ void __launch_bounds__(256) zero_out_kernel(float4* __restrict__ out4)
{
    int i = blockIdx.x * 256 + threadIdx.x;
    out4[i] = make_float4(0.f, 0.f, 0.f, 0.f);
}

// ---------------- router: logits, softmax, top-2, weights ----------------
__global__ void __launch_bounds__(256) router_kernel(const float* __restrict__ x,
                                                     const float* __restrict__ gw)
{
    int t = blockIdx.x;
    const float* xr = x + (size_t)t * DDIM;
    __shared__ float sred[NEXP][256];
    float acc[NEXP];
#pragma unroll
    for (int e = 0; e < NEXP; e++) acc[e] = 0.f;
    for (int d = threadIdx.x; d < DDIM; d += 256) {
        float xv = xr[d];
#pragma unroll
        for (int e = 0; e < NEXP; e++) acc[e] += xv * gw[e*DDIM + d];
    }
#pragma unroll
    for (int e = 0; e < NEXP; e++) sred[e][threadIdx.x] = acc[e];
    __syncthreads();
    for (int s = 128; s > 0; s >>= 1) {
        if (threadIdx.x < s) {
#pragma unroll
            for (int e = 0; e < NEXP; e++) sred[e][threadIdx.x] += sred[e][threadIdx.x + s];
        }
        __syncthreads();
    }
    if (threadIdx.x == 0) {
        float lg[NEXP];
#pragma unroll
        for (int e = 0; e < NEXP; e++) lg[e] = sred[e][0];
        float mx = lg[0];
#pragma unroll
        for (int e = 1; e < NEXP; e++) mx = fmaxf(mx, lg[e]);
        float se = 0.f, p[NEXP];
#pragma unroll
        for (int e = 0; e < NEXP; e++) { p[e] = expf(lg[e] - mx); se += p[e]; }
        float inv = 1.f / se;
#pragma unroll
        for (int e = 0; e < NEXP; e++) { p[e] *= inv; g_probs[t*NEXP + e] = p[e]; }
        g_lse[t] = mx + logf(se);
        int i0 = 0;
#pragma unroll
        for (int e = 1; e < NEXP; e++) if (p[e] > p[i0]) i0 = e;
        int i1 = -1;
#pragma unroll
        for (int e = 0; e < NEXP; e++) {
            if (e == i0) continue;
            if (i1 < 0 || p[e] > p[i1]) i1 = e;
        }
        float s2 = p[i0] + p[i1];
        g_eids[t*2 + 0] = i0; g_eids[t*2 + 1] = i1;
        g_ew[t*2 + 0] = p[i0] / s2; g_ew[t*2 + 1] = p[i1] / s2;
    }
}

// ---------------- rank + clear + build fused (1024 threads, shfl-scan) ----------------
__global__ void __launch_bounds__(1024) rank_build_kernel()
{
    int k = blockIdx.x >> 3;
    int e = blockIdx.x & 7;
    int segbase = e*SLOTS_PER_E + k*CAP;
    int tid = threadIdx.x;
    for (int i = tid; i < CAP; i += 1024) {
        g_tok[segbase + i] = -1;
        g_wgt[segbase + i] = 0.f;
    }

    __shared__ int warp_sums[32];
    __shared__ int s_base;
    if (tid == 0) s_base = 0;
    __syncthreads();
    int lane = tid & 31, wid = tid >> 5;
    for (int c = 0; c < N_TOK; c += 1024) {
        int t = c + tid;
        int flag = (g_eids[t*2 + k] == e) ? 1 : 0;
        unsigned m = __ballot_sync(0xffffffffu, flag);
        int pre = __popc(m & ((1u << lane) - 1u));
        if (lane == 31) warp_sums[wid] = pre + flag;
        __syncthreads();
        if (wid == 0) {
            int v = warp_sums[lane];
#pragma unroll
            for (int o = 1; o < 32; o <<= 1) {
                int n = __shfl_up_sync(0xffffffffu, v, o);
                if (lane >= o) v += n;
            }
            warp_sums[lane] = v;   // inclusive scan
        }
        __syncthreads();
        int wbase = s_base + (wid ? warp_sums[wid-1] : 0);
        if (flag) {
            int r = wbase + pre;
            if (r < CAP) {
                g_tok[segbase + r] = t;
                g_wgt[segbase + r] = g_ew[t*2 + k];
            }
        }
        __syncthreads();
        if (tid == 0) s_base += warp_sums[31];
        __syncthreads();
    }
    if (tid == 0) g_cnt[k*NEXP + e] = s_base;
}

// ---------------- fused GEMM1 (fp16 mma + ldmatrix), per-expert, 256x(64+64) tile ----------------
// grid: (FDIM/64, SLOTS_PER_E/256), block 512, dyn smem
__global__ void __launch_bounds__(512, 1) gemm1_h(int e)
{
    int m0 = blockIdx.y * 256;
    int seg = (m0 >= CAP) ? 1 : 0;
    int lim = min(g_cnt[seg*NEXP + e], CAP);
    if ((m0 - seg*CAP) >= lim) return;

    int n0 = blockIdx.x * 64;

    extern __shared__ __half smh[];
    unsigned smu = (unsigned)__cvta_generic_to_shared(smh);

    int tid = threadIdx.x;
    int ar = tid >> 1;
    int hc = (tid & 1) * 16;
    int tok = g_tok[e*SLOTS_PER_E + m0 + ar];
    const __half* ap = g_xh + (size_t)max(tok, 0) * DDIM + hc;
    int abytes = (tok >= 0) ? 16 : 0;
    int br = tid >> 2;
    int bo = (tid & 3) * 8;
    const __half* bp = (br < 64)
        ? (g_wgh + ((size_t)e*FDIM + n0 + br) * DDIM + bo)
        : (g_wuh + ((size_t)e*FDIM + n0 + (br - 64)) * DDIM + bo);

    const int KT = DDIM / BKH;           // 32

#pragma unroll
    for (int s = 0; s < STAGES-1; s++) {
        __half* sA = smh + s*STG_H + ar*HSTRIDE + hc;
        __half* sB = smh + s*STG_H + ASTG + br*HSTRIDE + bo;
        int k0 = s * BKH;
        cp_async16(sA,      ap + k0,      abytes);
        cp_async16(sA + 8,  ap + k0 + 8,  abytes);
        cp_async16(sB,      bp + k0,      16);
        cp_commit();
    }

    float accg[4][2][4], accu[4][2][4];
#pragma unroll
    for (int a = 0; a < 4; a++)
#pragma unroll
        for (int b = 0; b < 2; b++)
#pragma unroll
            for (int c = 0; c < 4; c++) { accg[a][b][c] = 0.f; accu[a][b][c] = 0.f; }

    int wid = tid >> 5, lane = tid & 31;
    int wm = wid & 3, wn = wid >> 2;      // 4 m-warps(64 rows) x 4 n-warps(16 cols)
    int g = lane >> 2, tg = lane & 3;
    int l8 = lane & 7, g1 = lane >> 3;

    unsigned aoff[4];
#pragma unroll
    for (int mt = 0; mt < 4; mt++)
        aoff[mt] = ((wm*64 + mt*16 + (g1 & 1)*8 + l8) * HSTRIDE + (g1 >> 1)*8) * 2;
    unsigned bgoff = ((wn*16 + (g1 >> 1)*8 + l8) * HSTRIDE + (g1 & 1)*8) * 2 + ASTG*2;
    unsigned buoff = ((64 + wn*16 + (g1 >> 1)*8 + l8) * HSTRIDE + (g1 & 1)*8) * 2 + ASTG*2;

    for (int kt = 0; kt < KT; kt++) {
        cp_wait();
        __syncthreads();
        int pf = kt + STAGES - 1;
        if (pf < KT) {
            int st = pf % STAGES;
            __half* sA = smh + st*STG_H + ar*HSTRIDE + hc;
            __half* sB = smh + st*STG_H + ASTG + br*HSTRIDE + bo;
            int k0 = pf * BKH;
            cp_async16(sA,      ap + k0,      abytes);
            cp_async16(sA + 8,  ap + k0 + 8,  abytes);
            cp_async16(sB,      bp + k0,      16);
        }
        cp_commit();
        unsigned stOff = smu + (kt % STAGES)*(STG_H*2);
#pragma unroll
        for (int kk = 0; kk < 2; kk++) {
            unsigned kb = kk * 32;
            unsigned af[4][4], bg[4], bu[4];
#pragma unroll
            for (int mt = 0; mt < 4; mt++) ldsm_x4(af[mt], stOff + aoff[mt] + kb);
            ldsm_x4(bg, stOff + bgoff + kb);
            ldsm_x4(bu, stOff + buoff + kb);
#pragma unroll
            for (int mt = 0; mt < 4; mt++) {
                mma_f16(accg[mt][0], af[mt], &bg[0]);
                mma_f16(accg[mt][1], af[mt], &bg[2]);
                mma_f16(accu[mt][0], af[mt], &bu[0]);
                mma_f16(accu[mt][1], af[mt], &bu[2]);
            }
        }
    }

    // epilogue: silu(g)*u -> fp16 store
#pragma unroll
    for (int mt = 0; mt < 4; mt++) {
        int r0 = m0 + wm*64 + mt*16 + g;
        __half* row0 = g_hh + ((size_t)e*SLOTS_PER_E + r0) * FDIM;
        __half* row1 = g_hh + ((size_t)e*SLOTS_PER_E + r0 + 8) * FDIM;
#pragma unroll
        for (int nt = 0; nt < 2; nt++) {
            int c0 = n0 + wn*16 + nt*8 + tg*2;
            float2 v0, v1;
            v0.x = silu_mul(accg[mt][nt][0], accu[mt][nt][0]);
            v0.y = silu_mul(accg[mt][nt][1], accu[mt][nt][1]);
            v1.x = silu_mul(accg[mt][nt][2], accu[mt][nt][2]);
            v1.y = silu_mul(accg[mt][nt][3], accu[mt][nt][3]);
            *(__half2*)(row0 + c0) = __float22half2_rn(v0);
            *(__half2*)(row1 + c0) = __float22half2_rn(v1);
        }
    }
}

// ---------------- GEMM2 (fp16 mma + ldmatrix), 256x128 tile — vector-red accumulate ----------------
// grid: (DDIM/128, SLOTS_PER_E/256, NEXP), block 512, dyn smem
__global__ void __launch_bounds__(512, 1) gemm2_h(float* __restrict__ out)
{
    int e = blockIdx.z;
    int m0 = blockIdx.y * 256;
    int seg = (m0 >= CAP) ? 1 : 0;
    int lim = min(g_cnt[seg*NEXP + e], CAP);
    if ((m0 - seg*CAP) >= lim) return;

    int n0 = blockIdx.x * 128;

    extern __shared__ __half smh[];
    unsigned smu = (unsigned)__cvta_generic_to_shared(smh);

    int tid = threadIdx.x;
    int ar = tid >> 1;
    int hc = (tid & 1) * 16;
    const __half* ap = g_hh + ((size_t)e*SLOTS_PER_E + m0 + ar) * FDIM + hc;
    int br = tid >> 2;
    int bo = (tid & 3) * 8;
    const __half* bp = g_woh + ((size_t)e*DDIM + n0 + br) * FDIM + bo;

    const int KT = FDIM / BKH;           // 128

#pragma unroll
    for (int s = 0; s < STAGES-1; s++) {
        __half* sA = smh + s*STG_H + ar*HSTRIDE + hc;
        __half* sB = smh + s*STG_H + ASTG + br*HSTRIDE + bo;
        int k0 = s * BKH;
        cp_async16(sA,     ap + k0,     16);
        cp_async16(sA + 8, ap + k0 + 8, 16);
        cp_async16(sB,     bp + k0,     16);
        cp_commit();
    }

    float acc[4][4][4];
#pragma unroll
    for (int a = 0; a < 4; a++)
#pragma unroll
        for (int b = 0; b < 4; b++)
#pragma unroll
            for (int c = 0; c < 4; c++) acc[a][b][c] = 0.f;

    int wid = tid >> 5, lane = tid & 31;
    int wm = wid & 3, wn = wid >> 2;      // 4 m-warps(64 rows) x 4 n-warps(32 cols)
    int g = lane >> 2, tg = lane & 3;
    int l8 = lane & 7, g1 = lane >> 3;

    unsigned aoff[4];
#pragma unroll
    for (int mt = 0; mt < 4; mt++)
        aoff[mt] = ((wm*64 + mt*16 + (g1 & 1)*8 + l8) * HSTRIDE + (g1 >> 1)*8) * 2;
    unsigned boff[2];
#pragma unroll
    for (int p = 0; p < 2; p++)
        boff[p] = ((wn*32 + p*16 + (g1 >> 1)*8 + l8) * HSTRIDE + (g1 & 1)*8) * 2 + ASTG*2;

    for (int kt = 0; kt < KT; kt++) {
        cp_wait();
        __syncthreads();
        int pf = kt + STAGES - 1;
        if (pf < KT) {
            int st = pf % STAGES;
            __half* sA = smh + st*STG_H + ar*HSTRIDE + hc;
            __half* sB = smh + st*STG_H + ASTG + br*HSTRIDE + bo;
            int k0 = pf * BKH;
            cp_async16(sA,     ap + k0,     16);
            cp_async16(sA + 8, ap + k0 + 8, 16);
            cp_async16(sB,     bp + k0,     16);
        }
        cp_commit();
        unsigned stOff = smu + (kt % STAGES)*(STG_H*2);
#pragma unroll
        for (int kk = 0; kk < 2; kk++) {
            unsigned kb = kk * 32;
            unsigned af[4][4], b2[2][4];
#pragma unroll
            for (int mt = 0; mt < 4; mt++) ldsm_x4(af[mt], stOff + aoff[mt] + kb);
#pragma unroll
            for (int p = 0; p < 2; p++) ldsm_x4(b2[p], stOff + boff[p] + kb);
#pragma unroll
            for (int mt = 0; mt < 4; mt++)
#pragma unroll
                for (int p = 0; p < 2; p++) {
                    mma_f16(acc[mt][2*p+0], af[mt], &b2[p][0]);
                    mma_f16(acc[mt][2*p+1], af[mt], &b2[p][2]);
                }
        }
    }

    // epilogue: scaled vector-red accumulate directly into out
#pragma unroll
    for (int mt = 0; mt < 4; mt++) {
        int r0 = m0 + wm*64 + mt*16 + g;
        int slot0 = e*SLOTS_PER_E + r0;
        int t0 = g_tok[slot0];
        int t1 = g_tok[slot0 + 8];
        float w0 = g_wgt[slot0];
        float w1 = g_wgt[slot0 + 8];
        float* o0 = out + (size_t)max(t0, 0) * DDIM;
        float* o1 = out + (size_t)max(t1, 0) * DDIM;
#pragma unroll
        for (int nt = 0; nt < 4; nt++) {
            int c0 = n0 + wn*32 + nt*8 + tg*2;
            if (t0 >= 0) red_add_v2(o0 + c0, acc[mt][nt][0]*w0, acc[mt][nt][1]*w0);
            if (t1 >= 0) red_add_v2(o1 + c0, acc[mt][nt][2]*w1, acc[mt][nt][3]*w1);
        }
    }
}

// ---------------- aux loss: deterministic tree reduction ----------------
__global__ void __launch_bounds__(1024) aux_kernel(float* __restrict__ out_aux)
{
    __shared__ float sb[1024];
    __shared__ float res[9];
    int tid = threadIdx.x;
    float pacc[NEXP];
#pragma unroll
    for (int e = 0; e < NEXP; e++) pacc[e] = 0.f;
    float zacc = 0.f;
    for (int i = 0; i < N_TOK/1024; i++) {
        int t = tid * (N_TOK/1024) + i;
        const float* pr = g_probs + (size_t)t * NEXP;
#pragma unroll
        for (int e = 0; e < NEXP; e++) pacc[e] += pr[e];
        float l = g_lse[t];
        zacc += l * l;
    }
    for (int e = 0; e < NEXP; e++) {
        sb[tid] = pacc[e];
        __syncthreads();
        for (int s = 512; s > 0; s >>= 1) {
            if (tid < s) sb[tid] += sb[tid + s];
            __syncthreads();
        }
        if (tid == 0) res[e] = sb[0];
        __syncthreads();
    }
    sb[tid] = zacc;
    __syncthreads();
    for (int s = 512; s > 0; s >>= 1) {
        if (tid < s) sb[tid] += sb[tid + s];
        __syncthreads();
    }
    if (tid == 0) res[8] = sb[0];
    __syncthreads();
    if (tid == 0) {
        float lb = 0.f;
#pragma unroll
        for (int e = 0; e < NEXP; e++) {
            float density = (float)(g_cnt[e] + g_cnt[NEXP + e]) / (float)(N_TOK * 2);
            float mean_p = res[e] / (float)N_TOK;
            lb += density * mean_p;
        }
        lb *= 0.01f * (float)NEXP;
        float z = 0.001f * (res[8] / (float)N_TOK);
        out_aux[0] = lb + z;
    }
}

// ---------------- launch (dual-stream per-expert gemm1 to fill wave tails) ----------------
extern "C" void kernel_launch(void* const* d_in, const int* in_sizes, int n_in,
                              void* d_out, int out_size)
{
    const float* x       = (const float*)d_in[0];
    const float* gate_w  = (const float*)d_in[1];
    const float* wi_gate = (const float*)d_in[2];
    const float* wi_up   = (const float*)d_in[3];
    const float* wo      = (const float*)d_in[4];
    float* out = (float*)d_out;

    static bool s_init = false;
    static cudaStream_t s2, s3;
    static cudaEvent_t evRoot, evW[NEXP], evG1[NEXP], evB, evR, evC;
    if (!s_init) {
        cudaFuncSetAttribute(gemm1_h, cudaFuncAttributeMaxDynamicSharedMemorySize, SMEM_BYTES);
        cudaFuncSetAttribute(gemm2_h, cudaFuncAttributeMaxDynamicSharedMemorySize, SMEM_BYTES);
        cudaStreamCreateWithFlags(&s2, cudaStreamNonBlocking);
        cudaStreamCreateWithFlags(&s3, cudaStreamNonBlocking);
        cudaEventCreateWithFlags(&evRoot, cudaEventDisableTiming);
        for (int e = 0; e < NEXP; e++) {
            cudaEventCreateWithFlags(&evW[e],  cudaEventDisableTiming);
            cudaEventCreateWithFlags(&evG1[e], cudaEventDisableTiming);
        }
        cudaEventCreateWithFlags(&evB, cudaEventDisableTiming);
        cudaEventCreateWithFlags(&evR, cudaEventDisableTiming);
        cudaEventCreateWithFlags(&evC, cudaEventDisableTiming);
        s_init = true;
    }

    // fork
    cudaEventRecord(evRoot, 0);
    cudaStreamWaitEvent(s2, evRoot, 0);
    cudaStreamWaitEvent(s3, evRoot, 0);

    // s2: x convert, then per-expert weight converts (event per expert)
    conv_x<<<512, 256, 0, s2>>>((const float2*)x);
    for (int e = 0; e < NEXP; e++) {
        conv_wgu_e<<<1024, 256, 0, s2>>>((const float2*)wi_gate, (const float2*)wi_up, e);
        cudaEventRecord(evW[e], s2);
    }
    conv_wo<<<1024, 256, 0, s2>>>((const float2*)wo);
    zero_out_kernel<<<(N_TOK*DDIM/4)/256, 256, 0, s2>>>((float4*)out);
    cudaEventRecord(evB, s2);

    // main: routing
    router_kernel<<<N_TOK, 256>>>(x, gate_w);
    rank_build_kernel<<<16, 1024>>>();
    cudaEventRecord(evR, 0);

    // s2: aux loss (needs probs/lse/cnt only), overlapped with GEMMs
    if (out_size > N_TOK * DDIM) {
        cudaStreamWaitEvent(s2, evR, 0);
        aux_kernel<<<1, 1024, 0, s2>>>(out + (size_t)N_TOK * DDIM);
    }
    cudaEventRecord(evC, s2);

    // per-expert gemm1 round-robined across main stream and s3 to fill wave tails
    cudaStreamWaitEvent(s3, evR, 0);   // s3 gemm1 needs routing done
    for (int e = 0; e < NEXP; e++) {
        cudaStream_t st = (e & 1) ? s3 : (cudaStream_t)0;
        cudaStreamWaitEvent(st, evW[e], 0);
        gemm1_h<<<dim3(FDIM/64, SLOTS_PER_E/256), 512, SMEM_BYTES, st>>>(e);
        if (e & 1) cudaEventRecord(evG1[e], s3);
    }

    // gemm2 (main stream): even experts' gemm1 ordered implicitly; wait odd ones + wo/zero
    for (int e = 1; e < NEXP; e += 2) cudaStreamWaitEvent(0, evG1[e], 0);
    cudaStreamWaitEvent(0, evB, 0);
    gemm2_h<<<dim3(DDIM/128, SLOTS_PER_E/256, NEXP), 512, SMEM_BYTES>>>(out);

    // join side stream back (aux) before capture ends
    cudaStreamWaitEvent(0, evC, 0);
}